// round 4
// baseline (speedup 1.0000x reference)
#include <cuda_runtime.h>

#define FFT_N  4096
#define NT     256
#define PAD(i) ((i) + ((i) >> 4))
#define SMEM_E (FFT_N + (FFT_N >> 4))   // 4352 cplx = 34816 B

typedef unsigned long long cplx;   // packed (float re, float im)

// ---------- packed f32x2 helpers ----------
__device__ __forceinline__ cplx cpack(float x, float y) {
    cplx r; asm("mov.b64 %0,{%1,%2};" : "=l"(r) : "f"(x), "f"(y)); return r;
}
__device__ __forceinline__ void cunp(cplx a, float& x, float& y) {
    asm("mov.b64 {%0,%1},%2;" : "=f"(x), "=f"(y) : "l"(a));
}
__device__ __forceinline__ cplx cadd(cplx a, cplx b) {
    cplx r; asm("add.rn.f32x2 %0,%1,%2;" : "=l"(r) : "l"(a), "l"(b)); return r;
}
__device__ __forceinline__ cplx csub(cplx a, cplx b) {   // a - b = fma(b, (-1,-1), a)
    cplx r, n = cpack(-1.0f, -1.0f);
    asm("fma.rn.f32x2 %0,%1,%2,%3;" : "=l"(r) : "l"(b), "l"(n), "l"(a)); return r;
}
__device__ __forceinline__ cplx cmulp(cplx a, cplx b) {  // elementwise (ax*bx, ay*by)
    cplx r; asm("mul.rn.f32x2 %0,%1,%2;" : "=l"(r) : "l"(a), "l"(b)); return r;
}
// complex multiply by runtime scalar pair (wr, wi)
__device__ __forceinline__ cplx cmulw(cplx v, float wr, float wi) {
    float x, y; cunp(v, x, y);
    return cpack(fmaf(x, wr, -(y * wi)), fmaf(x, wi, y * wr));
}
// multiply by forward constant (cr, ci_fwd); DIR=+1 conjugates
template <int DIR>
__device__ __forceinline__ cplx cmulc(cplx v, float cr, float ci_fwd) {
    return cmulw(v, cr, (DIR < 0) ? ci_fwd : -ci_fwd);
}
// multiply by -i (DIR=-1) or +i (DIR=+1)
template <int DIR>
__device__ __forceinline__ cplx crotI(cplx z) {
    float x, y; cunp(z, x, y);
    return (DIR < 0) ? cpack(y, -x) : cpack(-y, x);
}

// ---------- radix-4 butterfly with fused rot-I pair ----------
template <int DIR>
__device__ __forceinline__ void dft4(cplx& a, cplx& b, cplx& c, cplx& d) {
    cplx t0 = cadd(a, c), t1 = csub(a, c);
    cplx t2 = cadd(b, d), u = csub(b, d);
    a = cadd(t0, t2);
    c = csub(t0, t2);
    // b = t1 + DIR_rot(u), d = t1 - DIR_rot(u); rot fwd: (u.y, -u.x)
    float tx, ty, ux, uy;
    cunp(t1, tx, ty); cunp(u, ux, uy);
    if (DIR < 0) {
        b = cpack(tx + uy, ty - ux);
        d = cpack(tx - uy, ty + ux);
    } else {
        b = cpack(tx - uy, ty + ux);
        d = cpack(tx + uy, ty - ux);
    }
}

// 16-point DFT as 4x4. Input natural order; X[k1 + 4*k2] lands at v[4*k1 + k2].
#define OUT(q) ((((q) & 3) << 2) | ((q) >> 2))

template <int DIR>
__device__ __forceinline__ void dft16(cplx v[16]) {
    const float C1 = 0.92387953251128675613f;   // cos(pi/8)
    const float S1 = 0.38268343236508977173f;   // sin(pi/8)
    const float H  = 0.70710678118654752440f;
    dft4<DIR>(v[0], v[4], v[8],  v[12]);
    dft4<DIR>(v[1], v[5], v[9],  v[13]);
    dft4<DIR>(v[2], v[6], v[10], v[14]);
    dft4<DIR>(v[3], v[7], v[11], v[15]);
    v[5]  = cmulc<DIR>(v[5],  C1, -S1);   // W16^1
    v[6]  = cmulc<DIR>(v[6],  H,  -H );   // W16^2
    v[7]  = cmulc<DIR>(v[7],  S1, -C1);   // W16^3
    v[9]  = cmulc<DIR>(v[9],  H,  -H );   // W16^2
    v[10] = crotI<DIR>(v[10]);            // W16^4
    v[11] = cmulc<DIR>(v[11], -H, -H );   // W16^6
    v[13] = cmulc<DIR>(v[13], S1, -C1);   // W16^3
    v[14] = cmulc<DIR>(v[14], -H, -H );   // W16^6
    v[15] = cmulc<DIR>(v[15], -C1, S1);   // W16^9
    dft4<DIR>(v[0],  v[1],  v[2],  v[3]);
    dft4<DIR>(v[4],  v[5],  v[6],  v[7]);
    dft4<DIR>(v[8],  v[9],  v[10], v[11]);
    dft4<DIR>(v[12], v[13], v[14], v[15]);
}

// Twiddle ladder: v[r] *= exp(i*theta*r), r=1..15. Two 8-step chains (MUFU anchors).
__device__ __forceinline__ void twiddle_ladder(cplx v[16], float theta) {
    float s1, c1, s8, c8;
    __sincosf(theta, &s1, &c1);
    __sincosf(8.0f * theta, &s8, &c8);
    float ar = c1, ai = s1;          // chain A: r = 1..7
    float br = c8, bi = s8;          // chain B: r = 8..15
    v[8] = cmulw(v[8], br, bi);
#pragma unroll
    for (int r = 1; r < 8; r++) {
        v[r] = cmulw(v[r], ar, ai);
        float nbr = fmaf(br, c1, -(bi * s1));
        bi = fmaf(br, s1, bi * c1);
        br = nbr;
        v[8 + r] = cmulw(v[8 + r], br, bi);
        if (r < 7) {
            float nar = fmaf(ar, c1, -(ai * s1));
            ai = fmaf(ar, s1, ai * c1);
            ar = nar;
        }
    }
}

// Middle Stockham radix-16 stage, in-place smem
template <int S, int DIR>
__device__ __forceinline__ void mid_stage(cplx* sm, int i) {
    cplx v[16];
#pragma unroll
    for (int r = 0; r < 16; r++) v[r] = sm[PAD(i + NT * r)];
    int k = i & (S - 1);
    float theta = ((DIR < 0) ? -6.283185307179586f : 6.283185307179586f)
                  * (float)k / (float)(16 * S);
    twiddle_ladder(v, theta);
    dft16<DIR>(v);
    __syncthreads();
    int j = ((i & ~(S - 1)) << 4) + k;
#pragma unroll
    for (int q = 0; q < 16; q++) sm[PAD(j + q * S)] = v[OUT(q)];
    __syncthreads();
}

extern __shared__ cplx sm[];

__global__ void __launch_bounds__(NT, 3)
afdf16p_kernel(const cplx* __restrict__ x, const cplx* __restrict__ A,
               const cplx* __restrict__ D, cplx* __restrict__ out) {
    const int i = threadIdx.x;
    const size_t base = (size_t)blockIdx.x * FFT_N;

    // ---- fwd stage 0 (S=1, twiddle-free) fused with gmem load + A scale ----
    {
        cplx v[16];
#pragma unroll
        for (int r = 0; r < 16; r++) {
            int c = i + NT * r;
            v[r] = cmulp(x[base + c], A[c]);   // independent re/im scale
        }
        dft16<-1>(v);
#pragma unroll
        for (int q = 0; q < 16; q++) sm[PAD(16 * i + q)] = v[OUT(q)];
    }
    __syncthreads();

    // ---- fwd stage 1 (S=16) ----
    mid_stage<16, -1>(sm, i);

    // ---- fwd stage 2 (S=256) + D-scale + inv stage 0, in registers ----
    {
        cplx u[16];
#pragma unroll
        for (int r = 0; r < 16; r++) u[r] = sm[PAD(i + NT * r)];
        twiddle_ladder(u, -6.283185307179586f * (float)i / (float)FFT_N);
        dft16<-1>(u);
        // u[OUT(q)] = F[i + 256*q]
        const cplx INVN = cpack(1.0f / (float)FFT_N, 1.0f / (float)FFT_N);
        cplx g[16];
#pragma unroll
        for (int r = 0; r < 16; r++) {
            g[r] = cmulp(cmulp(u[OUT(r)], D[i + NT * r]), INVN);
        }
        dft16<1>(g);   // inverse stage 0 over the stride-256 set we hold
        __syncthreads();
#pragma unroll
        for (int q = 0; q < 16; q++) sm[PAD(16 * i + q)] = g[OUT(q)];
    }
    __syncthreads();

    // ---- inv stage 1 (S=16) ----
    mid_stage<16, 1>(sm, i);

    // ---- inv stage 2 (S=256) -> gmem ----
    {
        cplx u[16];
#pragma unroll
        for (int r = 0; r < 16; r++) u[r] = sm[PAD(i + NT * r)];
        twiddle_ladder(u, 6.283185307179586f * (float)i / (float)FFT_N);
        dft16<1>(u);
#pragma unroll
        for (int q = 0; q < 16; q++) out[base + i + NT * q] = u[OUT(q)];
    }
}

extern "C" void kernel_launch(void* const* d_in, const int* in_sizes, int n_in,
                              void* d_out, int out_size) {
    const cplx* x = (const cplx*)d_in[0];
    const cplx* A = (const cplx*)d_in[1];
    const cplx* D = (const cplx*)d_in[2];
    cplx* out = (cplx*)d_out;

    int rows = in_sizes[0] / (FFT_N * 2);   // (B, C, 2) float32 -> B rows

    const int smem_bytes = SMEM_E * sizeof(cplx);  // 34816 B
    cudaFuncSetAttribute(afdf16p_kernel, cudaFuncAttributeMaxDynamicSharedMemorySize, smem_bytes);
    afdf16p_kernel<<<rows, NT, smem_bytes>>>(x, A, D, out);
}

// round 5
// speedup vs baseline: 1.0008x; 1.0008x over previous
#include <cuda_runtime.h>

#define FFT_N  4096
#define NT     512
#define PAD(i) ((i) + ((i) >> 4))
#define SMEM_E (FFT_N + (FFT_N >> 4))   // 4352 float2 = 34816 B

__device__ __forceinline__ float2 cadd(float2 a, float2 b) { return make_float2(a.x + b.x, a.y + b.y); }
__device__ __forceinline__ float2 csub(float2 a, float2 b) { return make_float2(a.x - b.x, a.y - b.y); }
__device__ __forceinline__ float2 cmul(float2 a, float2 b) {
    return make_float2(fmaf(a.x, b.x, -a.y * b.y), fmaf(a.x, b.y, a.y * b.x));
}
// multiply by -i (DIR=-1, forward) or +i (DIR=+1, inverse)
template <int DIR>
__device__ __forceinline__ float2 rotI(float2 z) {
    return (DIR < 0) ? make_float2(z.y, -z.x) : make_float2(-z.y, z.x);
}

// In-register 8-point DFT, natural order in and out. DIR=-1 fwd, +1 inv (unnormalized).
template <int DIR>
__device__ __forceinline__ void dft8(float2 v[8]) {
    const float h = 0.70710678118654752f;
    float2 t0 = cadd(v[0], v[4]), t1 = csub(v[0], v[4]);
    float2 t2 = cadd(v[2], v[6]), t3 = csub(v[2], v[6]);
    float2 u0 = cadd(v[1], v[5]), u1 = csub(v[1], v[5]);
    float2 u2 = cadd(v[3], v[7]), u3 = csub(v[3], v[7]);
    float2 e0 = cadd(t0, t2), e2 = csub(t0, t2);
    float2 rt3 = rotI<DIR>(t3);
    float2 e1 = cadd(t1, rt3), e3 = csub(t1, rt3);
    float2 o0 = cadd(u0, u2), o2 = csub(u0, u2);
    float2 ru3 = rotI<DIR>(u3);
    float2 o1 = cadd(u1, ru3), o3 = csub(u1, ru3);
    float2 w81 = (DIR < 0) ? make_float2(h, -h) : make_float2(h, h);
    float2 w83 = (DIR < 0) ? make_float2(-h, -h) : make_float2(-h, h);
    float2 a1 = cmul(o1, w81);
    float2 a2 = rotI<DIR>(o2);
    float2 a3 = cmul(o3, w83);
    v[0] = cadd(e0, o0); v[4] = csub(e0, o0);
    v[1] = cadd(e1, a1); v[5] = csub(e1, a1);
    v[2] = cadd(e2, a2); v[6] = csub(e2, a2);
    v[3] = cadd(e3, a3); v[7] = csub(e3, a3);
}

// v[r] *= exp(i*theta*r), r = 1..7 (serial chain from one MUFU sincos)
__device__ __forceinline__ void ladder8(float2 v[8], float theta) {
    float s1, c1;
    __sincosf(theta, &s1, &c1);
    float wr = c1, wi = s1;
    v[1] = cmul(v[1], make_float2(wr, wi));
#pragma unroll
    for (int r = 2; r < 8; r++) {
        float nr = fmaf(wr, c1, -(wi * s1));
        wi = fmaf(wr, s1, wi * c1);
        wr = nr;
        v[r] = cmul(v[r], make_float2(wr, wi));
    }
}

// Middle Stockham radix-8 stage, in-place smem. S = current span (8 or 64).
template <int S, int DIR>
__device__ __forceinline__ void mid_stage(float2* sm, int i) {
    float2 v[8];
#pragma unroll
    for (int r = 0; r < 8; r++) v[r] = sm[PAD(i + NT * r)];
    int k = i & (S - 1);
    float theta = ((DIR < 0) ? -6.283185307179586f : 6.283185307179586f)
                  * (float)k / (float)(8 * S);
    ladder8(v, theta);
    dft8<DIR>(v);
    __syncthreads();
    int j = ((i & ~(S - 1)) << 3) + k;   // (i/S)*8S + k
#pragma unroll
    for (int q = 0; q < 8; q++) sm[PAD(j + q * S)] = v[q];
    __syncthreads();
}

extern __shared__ float2 sm[];

__global__ void __launch_bounds__(NT, 3)
afdf8_kernel(const float2* __restrict__ x, const float2* __restrict__ A,
             const float2* __restrict__ D, float2* __restrict__ out) {
    const int i = threadIdx.x;
    const size_t base = (size_t)blockIdx.x * FFT_N;

    // ---- fwd stage 0 (S=1, twiddle-free) fused with gmem load + A scale ----
    {
        float2 v[8];
#pragma unroll
        for (int r = 0; r < 8; r++) {
            int c = i + NT * r;
            float2 xv = x[base + c];
            float2 a = A[c];
            v[r] = make_float2(a.x * xv.x, a.y * xv.y);  // independent re/im scale
        }
        dft8<-1>(v);
#pragma unroll
        for (int q = 0; q < 8; q++) sm[PAD(8 * i + q)] = v[q];
    }
    __syncthreads();

    // ---- fwd stage 1 (S=8), stage 2 (S=64) ----
    mid_stage<8, -1>(sm, i);
    mid_stage<64, -1>(sm, i);

    // ---- fwd stage 3 (S=512) + D scale + inv stage 0, all in registers ----
    {
        float2 v[8];
#pragma unroll
        for (int r = 0; r < 8; r++) v[r] = sm[PAD(i + NT * r)];
        ladder8(v, -6.283185307179586f * (float)i / (float)FFT_N);
        dft8<-1>(v);
        // v[q] = F[i + 512*q] (natural frequency order)
        const float invN = 1.0f / (float)FFT_N;
#pragma unroll
        for (int q = 0; q < 8; q++) {
            float2 d = D[i + NT * q];
            v[q] = make_float2(d.x * v[q].x * invN, d.y * v[q].y * invN);
        }
        dft8<1>(v);   // inverse stage 0 over the stride-512 set we hold
        __syncthreads();
#pragma unroll
        for (int q = 0; q < 8; q++) sm[PAD(8 * i + q)] = v[q];
    }
    __syncthreads();

    // ---- inv stage 1 (S=8), stage 2 (S=64) ----
    mid_stage<8, 1>(sm, i);
    mid_stage<64, 1>(sm, i);

    // ---- inv stage 3 (S=512) -> gmem, coalesced ----
    {
        float2 v[8];
#pragma unroll
        for (int r = 0; r < 8; r++) v[r] = sm[PAD(i + NT * r)];
        ladder8(v, 6.283185307179586f * (float)i / (float)FFT_N);
        dft8<1>(v);
#pragma unroll
        for (int q = 0; q < 8; q++) out[base + i + NT * q] = v[q];
    }
}

extern "C" void kernel_launch(void* const* d_in, const int* in_sizes, int n_in,
                              void* d_out, int out_size) {
    const float2* x = (const float2*)d_in[0];
    const float2* A = (const float2*)d_in[1];
    const float2* D = (const float2*)d_in[2];
    float2* out = (float2*)d_out;

    int rows = in_sizes[0] / (FFT_N * 2);   // (B, C, 2) float32 -> B rows

    const int smem_bytes = SMEM_E * sizeof(float2);  // 34816 B
    cudaFuncSetAttribute(afdf8_kernel, cudaFuncAttributeMaxDynamicSharedMemorySize, smem_bytes);
    afdf8_kernel<<<rows, NT, smem_bytes>>>(x, A, D, out);
}